// round 5
// baseline (speedup 1.0000x reference)
#include <cuda_runtime.h>
#include <cstdint>

#define NB   4
#define CCH  512
#define NPIX 2304
#define CR   64
#define CH4  128
#define HW   48
#define KCONV 4608   // 512*9

// ---------------- scratch (device globals; no dynamic allocation) ----------------
__device__ float g_q[NB*CR*NPIX];
__device__ float g_k[NB*CR*NPIX];
__device__ float g_v[NB*CCH*NPIX];
__device__ float g_E[(size_t)NB*NPIX*NPIX];      // energy
__device__ float g_A[(size_t)NB*NPIX*NPIX];      // materialized attention (reused per pass)
__device__ float g_stats[6*NB*NPIX];             // [variant][max|invsum][B*N]
__device__ float g_buf0[NB*CCH*NPIX];            // out0 (post conv1)
__device__ float g_buf1[NB*CCH*NPIX];            // pre-conv temp
__device__ float g_out1[NB*CCH*NPIX];            // out1 (post conv2)
__device__ float g_vchl[NB*CCH*NPIX];            // chl output (v1 / v2)
__device__ float g_qc[NB*CH4*NPIX];
__device__ float g_E2[NB*CH4*CCH];
__device__ float g_expand[NB*CCH*CCH];
__device__ float g_attnc[NB*CCH*CCH];

// ---------------- reductions ----------------
__device__ __forceinline__ float warpMax(float v){
  #pragma unroll
  for (int o=16;o;o>>=1) v = fmaxf(v, __shfl_xor_sync(0xffffffffu, v, o));
  return v;
}
__device__ __forceinline__ float warpMin(float v){
  #pragma unroll
  for (int o=16;o;o>>=1) v = fminf(v, __shfl_xor_sync(0xffffffffu, v, o));
  return v;
}
__device__ __forceinline__ float warpSum(float v){
  #pragma unroll
  for (int o=16;o;o>>=1) v += __shfl_xor_sync(0xffffffffu, v, o);
  return v;
}
__device__ float blockMax(float v, float* sh){
  v = warpMax(v);
  if ((threadIdx.x & 31) == 0) sh[threadIdx.x >> 5] = v;
  __syncthreads();
  if (threadIdx.x < 32){
    float t = (threadIdx.x < (blockDim.x>>5)) ? sh[threadIdx.x] : -3.4e38f;
    t = warpMax(t);
    if (threadIdx.x == 0) sh[0] = t;
  }
  __syncthreads();
  float r = sh[0];
  __syncthreads();
  return r;
}
__device__ float blockMin(float v, float* sh){
  v = warpMin(v);
  if ((threadIdx.x & 31) == 0) sh[threadIdx.x >> 5] = v;
  __syncthreads();
  if (threadIdx.x < 32){
    float t = (threadIdx.x < (blockDim.x>>5)) ? sh[threadIdx.x] : 3.4e38f;
    t = warpMin(t);
    if (threadIdx.x == 0) sh[0] = t;
  }
  __syncthreads();
  float r = sh[0];
  __syncthreads();
  return r;
}
__device__ float blockSum(float v, float* sh){
  v = warpSum(v);
  if ((threadIdx.x & 31) == 0) sh[threadIdx.x >> 5] = v;
  __syncthreads();
  if (threadIdx.x < 32){
    float t = (threadIdx.x < (blockDim.x>>5)) ? sh[threadIdx.x] : 0.f;
    t = warpSum(t);
    if (threadIdx.x == 0) sh[0] = t;
  }
  __syncthreads();
  float r = sh[0];
  __syncthreads();
  return r;
}

// ---------------- mma / cp.async helpers ----------------
__device__ __forceinline__ void mma_tf32(float* c, const uint32_t* a, const uint32_t* b){
  asm volatile("mma.sync.aligned.m16n8k8.row.col.f32.tf32.tf32.f32 "
    "{%0,%1,%2,%3}, {%4,%5,%6,%7}, {%8,%9}, {%0,%1,%2,%3};\n"
    : "+f"(c[0]), "+f"(c[1]), "+f"(c[2]), "+f"(c[3])
    : "r"(a[0]), "r"(a[1]), "r"(a[2]), "r"(a[3]), "r"(b[0]), "r"(b[1]));
}
__device__ __forceinline__ void cpasync16(float* dst, const float* src, int szbytes){
  uint32_t d = (uint32_t)__cvta_generic_to_shared(dst);
  asm volatile("cp.async.cg.shared.global [%0], [%1], 16, %2;\n"
               :: "r"(d), "l"(src), "r"(szbytes));
}
__device__ __forceinline__ void cpasync4(float* dst, const float* src, int szbytes){
  uint32_t d = (uint32_t)__cvta_generic_to_shared(dst);
  asm volatile("cp.async.ca.shared.global [%0], [%1], 4, %2;\n"
               :: "r"(d), "l"(src), "r"(szbytes));
}
__device__ __forceinline__ void cp_commit(){ asm volatile("cp.async.commit_group;\n"); }
__device__ __forceinline__ void cp_wait2(){ asm volatile("cp.async.wait_group 2;\n"); }

// split: hi = top-19-bit truncation (exact in tf32); lo = f - hi.
__device__ __forceinline__ void split_hl(float f, uint32_t& hi, uint32_t& lo){
  uint32_t u = __float_as_uint(f);
  hi = u & 0xffffe000u;
  lo = __float_as_uint(f - __uint_as_float(hi));
}

// ---------------- TF32 tensor-core GEMM, 4-stage cp.async pipeline, 3xTF32 ----------------
// MODE 0 = NN (A: MxK, B: KxN), 1 = TN (A: KxM, B: KxN), 2 = NT (A: MxK, B: NxK),
// MODE 3 = NN with implicit-im2col B (Bm = X (b,512,48,48), K = 4608).
// EPI  0 = optional per-row bias p0; 1 = relu(acc*p0[m]+p1[m]); 2 = gamma[0]*acc + res[m,n]
// Requirements: N % 128 == 0, K % 16 == 0, K >= 48. Block tile 128x128x16.
template<int MODE, int EPI>
__global__ void __launch_bounds__(256) gemm2_kernel(
    const float* __restrict__ A, long sA,
    const float* __restrict__ Bm, long sB,
    float* __restrict__ Cm, long sC,
    int M, int N, int K,
    const float* __restrict__ p0, const float* __restrict__ p1,
    const float* __restrict__ res, long sRes,
    const float* __restrict__ gamma)
{
  constexpr int AST   = (MODE==1) ? 136 : 20;
  constexpr int ASIZE = (MODE==1) ? 16*136 : 128*20;
  constexpr int BST   = (MODE==2) ? 20 : 136;
  constexpr int BSIZE = (MODE==2) ? 128*20 : 16*136;
  constexpr int STAGES = 4;

  extern __shared__ float smem[];
  float* Asm = smem;                    // STAGES * ASIZE
  float* Bsm = smem + STAGES*ASIZE;     // STAGES * BSIZE

  const int b = blockIdx.z;
  A  += (long)b * sA;
  Bm += (long)b * sB;
  Cm += (long)b * sC;
  if (EPI == 2) res += (long)b * sRes;

  const int tid  = threadIdx.x;
  const int warp = tid >> 5;
  const int lane = tid & 31;
  const int g    = lane >> 2;
  const int ct   = lane & 3;
  const int warpM = warp >> 2;       // 0..1
  const int warpN = warp & 3;        // 0..3
  const int m0 = blockIdx.y * 128;
  const int n0 = blockIdx.x * 128;

  float acc[4][4][4];
  #pragma unroll
  for (int i=0;i<4;i++)
    #pragma unroll
    for (int j=0;j<4;j++)
      #pragma unroll
      for (int c=0;c<4;c++) acc[i][j][c]=0.f;

  // ---- tile loaders ----
  auto loadA = [&](int stage, int k0){
    float* As = Asm + stage*ASIZE;
    #pragma unroll
    for (int c = tid; c < 512; c += 256){
      if (MODE != 1){
        int m = c >> 2, seg = (c & 3) * 4;
        int gm = m0 + m;
        int sz = (gm < M) ? 16 : 0;
        if (gm >= M) gm = M - 1;
        cpasync16(&As[m*AST + seg], A + (long)gm*K + k0 + seg, sz);
      } else {
        int k = c >> 5, seg = (c & 31) * 4;
        int gm = m0 + seg;
        int sz = (gm < M) ? 16 : 0;
        if (gm >= M) gm = 0;
        cpasync16(&As[k*AST + seg], A + (long)(k0+k)*M + m0 + ((sz)?seg:0), sz);
      }
    }
  };
  auto loadB = [&](int stage, int k0){
    float* Bs = Bsm + stage*BSIZE;
    if (MODE == 0 || MODE == 1){
      #pragma unroll
      for (int c = tid; c < 512; c += 256){
        int k = c >> 5, seg = (c & 31) * 4;
        cpasync16(&Bs[k*BST + seg], Bm + (long)(k0+k)*N + n0 + seg, 16);
      }
    } else if (MODE == 2){
      #pragma unroll
      for (int c = tid; c < 512; c += 256){
        int n = c >> 2, seg = (c & 3) * 4;
        cpasync16(&Bs[n*BST + seg], Bm + (long)(n0+n)*K + k0 + seg, 16);
      }
    } else { // MODE 3: implicit im2col from X (b,512,48,48)
      #pragma unroll
      for (int j = 0; j < 8; j++){
        int e = tid + 256*j;          // 0..2047
        int k = e >> 7, n = e & 127;
        int gk = k0 + k;
        int ic = gk / 9;
        int kk = gk - ic*9;
        int ky = kk/3, kx = kk - (kk/3)*3;
        int np = n0 + n;
        int y  = np/HW + ky - 1;
        int xx = np - (np/HW)*HW + kx - 1;
        bool ok = (y >= 0 && y < HW && xx >= 0 && xx < HW);
        const float* src = Bm + (long)ic*NPIX + (ok ? (y*HW + xx) : 0);
        cpasync4(&Bs[k*BST + n], src, ok ? 4 : 0);
      }
    }
  };

  const int T = K / 16;   // all call sites have T >= 4
  loadA(0, 0);  loadB(0, 0);  cp_commit();
  loadA(1, 16); loadB(1, 16); cp_commit();
  loadA(2, 32); loadB(2, 32); cp_commit();

  for (int i = 0; i < T; i++){
    cp_wait2();
    __syncthreads();
    if (i + 3 < T){ loadA((i+3)&3, (i+3)*16); loadB((i+3)&3, (i+3)*16); }
    cp_commit();

    const int cur = i & 3;
    const float* As = Asm + cur*ASIZE;
    const float* Bs = Bsm + cur*BSIZE;

    #pragma unroll
    for (int kk = 0; kk < 2; kk++){
      const int kb = kk*8;
      float a32[4][4], b32[4][2];
      #pragma unroll
      for (int mi=0; mi<4; mi++){
        int r = warpM*64 + mi*16 + g;
        if (MODE != 1){
          a32[mi][0] = As[(r   )*AST + kb+ct  ];
          a32[mi][1] = As[(r+8 )*AST + kb+ct  ];
          a32[mi][2] = As[(r   )*AST + kb+ct+4];
          a32[mi][3] = As[(r+8 )*AST + kb+ct+4];
        } else {
          a32[mi][0] = As[(kb+ct  )*AST + r  ];
          a32[mi][1] = As[(kb+ct  )*AST + r+8];
          a32[mi][2] = As[(kb+ct+4)*AST + r  ];
          a32[mi][3] = As[(kb+ct+4)*AST + r+8];
        }
      }
      #pragma unroll
      for (int nj=0; nj<4; nj++){
        int cl = warpN*32 + nj*8 + g;
        if (MODE != 2){
          b32[nj][0] = Bs[(kb+ct  )*BST + cl];
          b32[nj][1] = Bs[(kb+ct+4)*BST + cl];
        } else {
          b32[nj][0] = Bs[cl*BST + kb+ct  ];
          b32[nj][1] = Bs[cl*BST + kb+ct+4];
        }
      }
      uint32_t ah[4][4], al[4][4], bh[4][2], bl[4][2];
      #pragma unroll
      for (int mi=0; mi<4; mi++)
        #pragma unroll
        for (int c=0; c<4; c++) split_hl(a32[mi][c], ah[mi][c], al[mi][c]);
      #pragma unroll
      for (int nj=0; nj<4; nj++)
        #pragma unroll
        for (int c=0; c<2; c++) split_hl(b32[nj][c], bh[nj][c], bl[nj][c]);
      #pragma unroll
      for (int mi=0; mi<4; mi++)
        #pragma unroll
        for (int nj=0; nj<4; nj++){
          mma_tf32(acc[mi][nj], ah[mi], bh[nj]);
          mma_tf32(acc[mi][nj], ah[mi], bl[nj]);
          mma_tf32(acc[mi][nj], al[mi], bh[nj]);
        }
    }
  }

  __syncthreads();

  // ---- epilogue
  #pragma unroll
  for (int mi=0; mi<4; mi++){
    int r0 = m0 + warpM*64 + mi*16 + g;
    int r1 = r0 + 8;
    float s0=0.f, o0=0.f, s1=0.f, o1=0.f;
    if (EPI == 1){
      if (r0 < M){ s0 = p0[r0]; o0 = p1[r0]; }
      if (r1 < M){ s1 = p0[r1]; o1 = p1[r1]; }
    } else if (EPI == 0){
      if (p0){ if (r0 < M) o0 = p0[r0]; if (r1 < M) o1 = p0[r1]; }
    }
    #pragma unroll
    for (int nj=0; nj<4; nj++){
      int n = n0 + warpN*32 + nj*8 + 2*ct;
      if (r0 < M){
        float2 w;
        if (EPI == 0){ w.x = acc[mi][nj][0] + o0; w.y = acc[mi][nj][1] + o0; }
        else if (EPI == 1){
          w.x = fmaxf(acc[mi][nj][0]*s0 + o0, 0.f);
          w.y = fmaxf(acc[mi][nj][1]*s0 + o0, 0.f);
        } else {
          float2 rr = *(const float2*)&res[(long)r0*N + n];
          w.x = gamma[0]*acc[mi][nj][0] + rr.x;
          w.y = gamma[0]*acc[mi][nj][1] + rr.y;
        }
        *(float2*)&Cm[(long)r0*N + n] = w;
      }
      if (r1 < M){
        float2 w;
        if (EPI == 0){ w.x = acc[mi][nj][2] + o1; w.y = acc[mi][nj][3] + o1; }
        else if (EPI == 1){
          w.x = fmaxf(acc[mi][nj][2]*s1 + o1, 0.f);
          w.y = fmaxf(acc[mi][nj][3]*s1 + o1, 0.f);
        } else {
          float2 rr = *(const float2*)&res[(long)r1*N + n];
          w.x = gamma[0]*acc[mi][nj][2] + rr.x;
          w.y = gamma[0]*acc[mi][nj][3] + rr.y;
        }
        *(float2*)&Cm[(long)r1*N + n] = w;
      }
    }
  }
}

// ---------------- softmax row stats (3 variants, one pass) ----------------
__global__ __launch_bounds__(256) void softmax_stats_kernel(
    const float* __restrict__ E, const float* __restrict__ M1,
    const float* __restrict__ M2, float* __restrict__ st)
{
  __shared__ float sh[32];
  const int R = NB*NPIX;
  int row = blockIdx.x;            // b*N + m
  int mr  = row % NPIX;
  const float* e  = E  + (long)row * NPIX;
  const float* m1 = M1 + (long)mr  * NPIX;
  const float* m2 = M2 + (long)mr  * NPIX;
  int tid = threadIdx.x;

  float ev[9], w1[9], w2[9];
  float mx0=-3.4e38f, mx1=-3.4e38f, mx2=-3.4e38f;
  #pragma unroll
  for (int i=0;i<9;i++){
    int n = tid + i*256;
    ev[i]=e[n]; w1[i]=m1[n]; w2[i]=m2[n];
    mx0 = fmaxf(mx0, ev[i]);
    if (w1[i] > 0.f) mx1 = fmaxf(mx1, ev[i]);
    if (w2[i] > 0.f) mx2 = fmaxf(mx2, ev[i]);
  }
  mx0 = blockMax(mx0, sh);
  mx1 = blockMax(mx1, sh);
  mx2 = blockMax(mx2, sh);
  float s0=0.f, s1=0.f, s2=0.f;
  #pragma unroll
  for (int i=0;i<9;i++){
    s0 += __expf(ev[i]-mx0);
    s1 += (w1[i] > 0.f) ? __expf(ev[i]-mx1) : 0.f;
    s2 += (w2[i] > 0.f) ? __expf(ev[i]-mx2) : 0.f;
  }
  s0 = blockSum(s0, sh);
  s1 = blockSum(s1, sh);
  s2 = blockSum(s2, sh);
  if (tid == 0){
    st[row]       = mx0;  st[R   + row] = 1.f/s0;
    st[2*R + row] = mx1;  st[3*R + row] = 1.f/s1;
    st[4*R + row] = mx2;  st[5*R + row] = 1.f/s2;
  }
}

// ---------------- materialize attention matrix ----------------
__global__ __launch_bounds__(256) void attn_mat_kernel(
    const float* __restrict__ E, const float* __restrict__ mask,
    const float* __restrict__ st, float* __restrict__ A, long total4)
{
  const long NN2 = (long)NPIX*NPIX;
  long i4 = (long)blockIdx.x * 256 + threadIdx.x;
  if (i4 >= total4) return;
  long idx = i4 * 4;
  int  b   = (int)(idx / NN2);
  long rem = idx - (long)b * NN2;
  int  mr  = (int)(rem / NPIX);
  float mx   = st[b*NPIX + mr];
  float rinv = st[NB*NPIX + b*NPIX + mr];
  float4 e = *(const float4*)&E[idx];
  float4 a;
  a.x = __expf(e.x-mx)*rinv;
  a.y = __expf(e.y-mx)*rinv;
  a.z = __expf(e.z-mx)*rinv;
  a.w = __expf(e.w-mx)*rinv;
  if (mask){
    float4 mk = *(const float4*)&mask[rem];
    if (mk.x <= 0.f) a.x = 0.f;
    if (mk.y <= 0.f) a.y = 0.f;
    if (mk.z <= 0.f) a.z = 0.f;
    if (mk.w <= 0.f) a.w = 0.f;
  }
  *(float4*)&A[idx] = a;
}

// ---------------- chl softmax: attn[o,c] = softmax_c(rowmax - expand[o,c]) ----------------
__global__ __launch_bounds__(256) void chl_softmax_kernel(
    const float* __restrict__ E, float* __restrict__ A)
{
  __shared__ float sh[32];
  long row = blockIdx.x;
  const float* e = E + row * CCH;
  float* a = A + row * CCH;
  int tid = threadIdx.x;
  float v0 = e[tid], v1 = e[tid+256];
  float mn = blockMin(fminf(v0, v1), sh);   // softmax(max-e) == exp(mn-e)/sum
  float t0 = __expf(mn - v0), t1 = __expf(mn - v1);
  float s = blockSum(t0 + t1, sh);
  float rinv = 1.f/s;
  a[tid]     = t0*rinv;
  a[tid+256] = t1*rinv;
}

// ---------------- host side ----------------
template<int MODE, int EPI>
static void rungemm(const float* A, long sA, const float* B, long sB, float* C, long sC,
                    int M, int N, int K,
                    const float* p0, const float* p1,
                    const float* res, long sRes, const float* gamma)
{
  constexpr int ASIZE = (MODE==1) ? 16*136 : 128*20;
  constexpr int BSIZE = (MODE==2) ? 128*20 : 16*136;
  constexpr int SMEM  = 4*(ASIZE+BSIZE)*(int)sizeof(float);
  cudaFuncSetAttribute(gemm2_kernel<MODE,EPI>,
                       cudaFuncAttributeMaxDynamicSharedMemorySize, SMEM);
  dim3 grid(N/128, (M+127)/128, NB);
  gemm2_kernel<MODE,EPI><<<grid, 256, SMEM>>>(A, sA, B, sB, C, sC, M, N, K,
                                              p0, p1, res, sRes, gamma);
}

static float* sym(const void* s){
  void* p = nullptr;
  cudaGetSymbolAddress(&p, s);
  return (float*)p;
}

extern "C" void kernel_launch(void* const* d_in, const int* in_sizes, int n_in,
                              void* d_out, int out_size)
{
  const float* x       = (const float*)d_in[0];
  const float* wq      = (const float*)d_in[1];
  const float* bq      = (const float*)d_in[2];
  const float* wk      = (const float*)d_in[3];
  const float* bk      = (const float*)d_in[4];
  const float* wv0     = (const float*)d_in[5];
  const float* bv0     = (const float*)d_in[6];
  const float* conv1_w = (const float*)d_in[7];
  const float* conv1_s = (const float*)d_in[8];
  const float* conv1_b = (const float*)d_in[9];
  const float* conv2_w = (const float*)d_in[10];
  const float* conv2_s = (const float*)d_in[11];
  const float* conv2_b = (const float*)d_in[12];
  const float* gamma   = (const float*)d_in[13];
  const float* gamma1  = (const float*)d_in[14];
  const float* gamma2  = (const float*)d_in[15];
  const float* c1_qw   = (const float*)d_in[16];
  const float* c1_qs   = (const float*)d_in[17];
  const float* c1_qb   = (const float*)d_in[18];
  const float* c1_ew   = (const float*)d_in[19];
  const float* c1_eb   = (const float*)d_in[20];
  const float* c2_qw   = (const float*)d_in[21];
  const float* c2_qs   = (const float*)d_in[22];
  const float* c2_qb   = (const float*)d_in[23];
  const float* c2_ew   = (const float*)d_in[24];
  const float* c2_eb   = (const float*)d_in[25];
  const float* mask1   = (const float*)d_in[26];
  const float* mask2   = (const float*)d_in[27];

  float* q    = sym(g_q);     float* k    = sym(g_k);     float* v     = sym(g_v);
  float* E    = sym(g_E);     float* A    = sym(g_A);     float* st    = sym(g_stats);
  float* buf0 = sym(g_buf0);  float* buf1 = sym(g_buf1);  float* out1  = sym(g_out1);
  float* vchl = sym(g_vchl);  float* qc   = sym(g_qc);    float* E2    = sym(g_E2);
  float* expd = sym(g_expand);float* attnc= sym(g_attnc);
  float* out  = (float*)d_out;

  const long sX  = (long)CCH*NPIX;
  const long sQ  = (long)CR*NPIX;
  const long sE  = (long)NPIX*NPIX;
  const long sQC = (long)CH4*NPIX;
  const long sE2 = (long)CH4*CCH;
  const long sCC = (long)CCH*CCH;
  const int  R   = NB*NPIX;
  const long total4 = (long)NB*NPIX*NPIX/4;
  const int  amg = (int)((total4 + 255)/256);

  // Q, K, V (1x1 convs)
  rungemm<0,0>(wq, 0, x, sX, q, sQ, CR,  NPIX, CCH, bq,  nullptr, nullptr, 0, nullptr);
  rungemm<0,0>(wk, 0, x, sX, k, sQ, CR,  NPIX, CCH, bk,  nullptr, nullptr, 0, nullptr);
  rungemm<0,0>(wv0,0, x, sX, v, sX, CCH, NPIX, CCH, bv0, nullptr, nullptr, 0, nullptr);

  // energy = Q^T K
  rungemm<1,0>(q, sQ, k, sQ, E, sE, NPIX, NPIX, CR, nullptr, nullptr, nullptr, 0, nullptr);

  // softmax stats for all 3 variants
  softmax_stats_kernel<<<R, 256>>>(E, mask1, mask2, st);

  // ---- pass 0 (unmasked) ----
  attn_mat_kernel<<<amg, 256>>>(E, nullptr, st, A, total4);
  rungemm<2,2>(v, sX, A, sE, buf1, sX, CCH, NPIX, NPIX, nullptr, nullptr, x, sX, gamma);
  rungemm<3,1>(conv1_w, 0, buf1, sX, buf0, sX, CCH, NPIX, KCONV, conv1_s, conv1_b, nullptr, 0, nullptr);

  // chl #1 on out0
  rungemm<0,1>(c1_qw, 0, buf0, sX, qc, sQC, CH4, NPIX, CCH, c1_qs, c1_qb, nullptr, 0, nullptr);
  rungemm<2,0>(qc, sQC, buf0, sX, E2, sE2, CH4, CCH, NPIX, nullptr, nullptr, nullptr, 0, nullptr);
  rungemm<0,0>(c1_ew, 0, E2, sE2, expd, sCC, CCH, CCH, CH4, c1_eb, nullptr, nullptr, 0, nullptr);
  chl_softmax_kernel<<<NB*CCH, 256>>>(expd, attnc);
  rungemm<0,0>(attnc, sCC, buf0, sX, vchl, sX, CCH, NPIX, CCH, nullptr, nullptr, nullptr, 0, nullptr);

  // ---- pass 1 (mask1) ----
  attn_mat_kernel<<<amg, 256>>>(E, mask1, st + 2*R, A, total4);
  rungemm<2,2>(vchl, sX, A, sE, buf1, sX, CCH, NPIX, NPIX, nullptr, nullptr, buf0, sX, gamma1);
  rungemm<3,1>(conv2_w, 0, buf1, sX, out1, sX, CCH, NPIX, KCONV, conv2_s, conv2_b, nullptr, 0, nullptr);

  // chl #2 on out1
  rungemm<0,1>(c2_qw, 0, out1, sX, qc, sQC, CH4, NPIX, CCH, c2_qs, c2_qb, nullptr, 0, nullptr);
  rungemm<2,0>(qc, sQC, out1, sX, E2, sE2, CH4, CCH, NPIX, nullptr, nullptr, nullptr, 0, nullptr);
  rungemm<0,0>(c2_ew, 0, E2, sE2, expd, sCC, CCH, CCH, CH4, c2_eb, nullptr, nullptr, 0, nullptr);
  chl_softmax_kernel<<<NB*CCH, 256>>>(expd, attnc);
  rungemm<0,0>(attnc, sCC, out1, sX, vchl, sX, CCH, NPIX, CCH, nullptr, nullptr, nullptr, 0, nullptr);

  // ---- pass 2 (mask2) -> final output ----
  attn_mat_kernel<<<amg, 256>>>(E, mask2, st + 4*R, A, total4);
  rungemm<2,2>(vchl, sX, A, sE, out, sX, CCH, NPIX, NPIX, nullptr, nullptr, out1, sX, gamma2);

  (void)in_sizes; (void)n_in; (void)out_size;
}

// round 6
// speedup vs baseline: 1.3934x; 1.3934x over previous
#include <cuda_runtime.h>
#include <cuda_bf16.h>
#include <cstdint>

#define NB   4
#define CCH  512
#define NPIX 2304
#define CR   64
#define CH4  128
#define HW   48
#define KCONV 4608

// ---------------- fp32 scratch ----------------
__device__ float g_E[(size_t)NB*NPIX*NPIX];
__device__ float g_stats[6*NB*NPIX];
__device__ float g_buf0[NB*CCH*NPIX];
__device__ float g_buf1[NB*CCH*NPIX];
__device__ float g_out1[NB*CCH*NPIX];
__device__ float g_expd[NB*CCH*CCH];

// ---------------- bf16 split scratch ----------------
__device__ __nv_bfloat16 g_wq_h[CR*CCH],  g_wq_l[CR*CCH];
__device__ __nv_bfloat16 g_wk_h[CR*CCH],  g_wk_l[CR*CCH];
__device__ __nv_bfloat16 g_wv_h[CCH*CCH], g_wv_l[CCH*CCH];
__device__ __nv_bfloat16 g_cw1_h[CCH*KCONV], g_cw1_l[CCH*KCONV];
__device__ __nv_bfloat16 g_cw2_h[CCH*KCONV], g_cw2_l[CCH*KCONV];
__device__ __nv_bfloat16 g_qw1_h[CH4*CCH], g_qw1_l[CH4*CCH];
__device__ __nv_bfloat16 g_qw2_h[CH4*CCH], g_qw2_l[CH4*CCH];
__device__ __nv_bfloat16 g_ew1_h[CCH*CH4], g_ew1_l[CCH*CH4];
__device__ __nv_bfloat16 g_ew2_h[CCH*CH4], g_ew2_l[CCH*CH4];
__device__ uint32_t g_xi_h[(size_t)NB*(CCH/2)*NPIX], g_xi_l[(size_t)NB*(CCH/2)*NPIX];
__device__ __nv_bfloat16 g_qT_h[NB*NPIX*CR], g_qT_l[NB*NPIX*CR];
__device__ __nv_bfloat16 g_k_h[NB*CR*NPIX],  g_k_l[NB*CR*NPIX];
__device__ __nv_bfloat16 g_v_h[NB*CCH*NPIX], g_v_l[NB*CCH*NPIX];
__device__ __nv_bfloat16 g_at_h[(size_t)NB*NPIX*NPIX], g_at_l[(size_t)NB*NPIX*NPIX];
__device__ uint32_t g_ci_h[(size_t)NB*(KCONV/2)*NPIX], g_ci_l[(size_t)NB*(KCONV/2)*NPIX];
__device__ __nv_bfloat16 g_b0_h[NB*CCH*NPIX], g_b0_l[NB*CCH*NPIX];
__device__ __nv_bfloat16 g_o1_h[NB*CCH*NPIX], g_o1_l[NB*CCH*NPIX];
__device__ __nv_bfloat16 g_qc_h[NB*CH4*NPIX], g_qc_l[NB*CH4*NPIX];
__device__ __nv_bfloat16 g_e2_h[NB*CH4*CCH],  g_e2_l[NB*CH4*CCH];
__device__ __nv_bfloat16 g_ac_h[NB*CCH*CCH],  g_ac_l[NB*CCH*CCH];
__device__ __nv_bfloat16 g_vc_h[NB*CCH*NPIX], g_vc_l[NB*CCH*NPIX];

// ---------------- reductions ----------------
__device__ __forceinline__ float warpMax(float v){
  #pragma unroll
  for (int o=16;o;o>>=1) v = fmaxf(v, __shfl_xor_sync(0xffffffffu, v, o));
  return v;
}
__device__ __forceinline__ float warpMin(float v){
  #pragma unroll
  for (int o=16;o;o>>=1) v = fminf(v, __shfl_xor_sync(0xffffffffu, v, o));
  return v;
}
__device__ __forceinline__ float warpSum(float v){
  #pragma unroll
  for (int o=16;o;o>>=1) v += __shfl_xor_sync(0xffffffffu, v, o);
  return v;
}
__device__ float blockMax(float v, float* sh){
  v = warpMax(v);
  if ((threadIdx.x & 31) == 0) sh[threadIdx.x >> 5] = v;
  __syncthreads();
  if (threadIdx.x < 32){
    float t = (threadIdx.x < (blockDim.x>>5)) ? sh[threadIdx.x] : -3.4e38f;
    t = warpMax(t);
    if (threadIdx.x == 0) sh[0] = t;
  }
  __syncthreads();
  float r = sh[0]; __syncthreads(); return r;
}
__device__ float blockMin(float v, float* sh){
  v = warpMin(v);
  if ((threadIdx.x & 31) == 0) sh[threadIdx.x >> 5] = v;
  __syncthreads();
  if (threadIdx.x < 32){
    float t = (threadIdx.x < (blockDim.x>>5)) ? sh[threadIdx.x] : 3.4e38f;
    t = warpMin(t);
    if (threadIdx.x == 0) sh[0] = t;
  }
  __syncthreads();
  float r = sh[0]; __syncthreads(); return r;
}
__device__ float blockSum(float v, float* sh){
  v = warpSum(v);
  if ((threadIdx.x & 31) == 0) sh[threadIdx.x >> 5] = v;
  __syncthreads();
  if (threadIdx.x < 32){
    float t = (threadIdx.x < (blockDim.x>>5)) ? sh[threadIdx.x] : 0.f;
    t = warpSum(t);
    if (threadIdx.x == 0) sh[0] = t;
  }
  __syncthreads();
  float r = sh[0]; __syncthreads(); return r;
}

// ---------------- helpers ----------------
__device__ __forceinline__ void mma_bf16(float* c, const uint32_t* a, const uint32_t* b){
  asm volatile("mma.sync.aligned.m16n8k16.row.col.f32.bf16.bf16.f32 "
    "{%0,%1,%2,%3}, {%4,%5,%6,%7}, {%8,%9}, {%0,%1,%2,%3};\n"
    : "+f"(c[0]), "+f"(c[1]), "+f"(c[2]), "+f"(c[3])
    : "r"(a[0]), "r"(a[1]), "r"(a[2]), "r"(a[3]), "r"(b[0]), "r"(b[1]));
}
__device__ __forceinline__ void cpasync16(void* dst, const void* src, int szbytes){
  uint32_t d = (uint32_t)__cvta_generic_to_shared(dst);
  asm volatile("cp.async.cg.shared.global [%0], [%1], 16, %2;\n"
               :: "r"(d), "l"(src), "r"(szbytes));
}
__device__ __forceinline__ void cp_commit(){ asm volatile("cp.async.commit_group;\n"); }
__device__ __forceinline__ void cp_wait1(){ asm volatile("cp.async.wait_group 1;\n"); }

__device__ __forceinline__ void bsplit(float v, __nv_bfloat16& h, __nv_bfloat16& l){
  h = __float2bfloat16(v);
  l = __float2bfloat16(v - __bfloat162float(h));
}
__device__ __forceinline__ uint32_t bpack(__nv_bfloat16 a, __nv_bfloat16 b){
  return (uint32_t)__bfloat16_as_ushort(a) | ((uint32_t)__bfloat16_as_ushort(b) << 16);
}

// ---------------- BF16x3 tensor-core GEMM ----------------
// A always bf16 [M][K] row-major (hi/lo arrays).
// BI: 0 = B bf16 [K][N] (k-major rows), 1 = B uint32 [K/2][N] (k-pair interleaved),
//     2 = B bf16 [N][K] (NT).
// EPI: 0 fp32 (+opt bias p0[m]); 2 fp32 gamma*acc+res; 3 relu(acc*p0+p1)->fp32+split;
//      4 relu->split only; 5 (+opt bias)->split only; 6 (+bias)->transposed split (ldT).
// Block tile 128x128x16; N%128==0, K%16==0, K>=32.
template<int BI, int EPI>
__global__ void __launch_bounds__(256,2) gemm3_kernel(
    const __nv_bfloat16* __restrict__ Ah, const __nv_bfloat16* __restrict__ Al, long sA,
    const void* __restrict__ Bh_, const void* __restrict__ Bl_, long sB,
    float* __restrict__ Cm, long sC,
    __nv_bfloat16* __restrict__ Dh, __nv_bfloat16* __restrict__ Dl, long sD,
    int M, int N, int K,
    const float* __restrict__ p0, const float* __restrict__ p1,
    const float* __restrict__ res, long sRes,
    const float* __restrict__ gamma, int ldT)
{
  constexpr int AROW = 24;         // bf16 stride per row (16 data + pad)
  constexpr int ABF  = 128*AROW;   // bf16 per A array per stage
  constexpr int ABYTES = 2*ABF*2;  // hi+lo bytes
  constexpr int BBYTES = (BI==2) ? 2*ABF*2 : 2*16*136*2;  // BI1: 2*8*136*4 = same
  constexpr int STAGEB = ABYTES + BBYTES;

  extern __shared__ char smc[];

  const int bz = blockIdx.z;
  Ah += (long)bz * sA;  Al += (long)bz * sA;
  const char* Bhp = (const char*)Bh_;
  const char* Blp = (const char*)Bl_;
  if (Cm) Cm += (long)bz * sC;
  if (EPI >= 3){ Dh += (long)bz * sD; Dl += (long)bz * sD; }
  if (EPI == 2) res += (long)bz * sRes;

  const int tid  = threadIdx.x;
  const int warp = tid >> 5;
  const int lane = tid & 31;
  const int g    = lane >> 2;
  const int ct   = lane & 3;
  const int warpM = warp >> 2;
  const int warpN = warp & 3;
  const int m0 = blockIdx.y * 128;
  const int n0 = blockIdx.x * 128;

  float acc[4][4][4];
  #pragma unroll
  for (int i=0;i<4;i++)
    #pragma unroll
    for (int j=0;j<4;j++)
      #pragma unroll
      for (int c=0;c<4;c++) acc[i][j][c]=0.f;

  auto loadT = [&](int s, int k0){
    char* st = smc + s*STAGEB;
    __nv_bfloat16* Ahs = (__nv_bfloat16*)st;
    // A (hi then lo)
    #pragma unroll
    for (int c = tid; c < 512; c += 256){
      const __nv_bfloat16* base = (c < 256) ? Ah : Al;
      __nv_bfloat16* dst = Ahs + ((c < 256) ? 0 : ABF);
      int e = c & 255, row = e >> 1, half = e & 1;
      int gm = m0 + row;
      int sz = (gm < M) ? 16 : 0; if (gm >= M) gm = 0;
      cpasync16(dst + row*AROW + half*8, base + (long)gm*K + k0 + half*8, sz);
    }
    char* bst = st + ABYTES;
    if (BI == 2){
      __nv_bfloat16* Bs = (__nv_bfloat16*)bst;
      const __nv_bfloat16* BH = (const __nv_bfloat16*)Bhp + (long)bz*sB;
      const __nv_bfloat16* BL = (const __nv_bfloat16*)Blp + (long)bz*sB;
      #pragma unroll
      for (int c = tid; c < 512; c += 256){
        const __nv_bfloat16* base = (c < 256) ? BH : BL;
        __nv_bfloat16* dst = Bs + ((c < 256) ? 0 : ABF);
        int e = c & 255, row = e >> 1, half = e & 1;
        cpasync16(dst + row*AROW + half*8, base + (long)(n0+row)*K + k0 + half*8, 16);
      }
    } else if (BI == 0){
      __nv_bfloat16* Bs = (__nv_bfloat16*)bst;
      const __nv_bfloat16* BH = (const __nv_bfloat16*)Bhp + (long)bz*sB;
      const __nv_bfloat16* BL = (const __nv_bfloat16*)Blp + (long)bz*sB;
      #pragma unroll
      for (int c = tid; c < 512; c += 256){
        const __nv_bfloat16* base = (c < 256) ? BH : BL;
        __nv_bfloat16* dst = Bs + ((c < 256) ? 0 : 16*136);
        int e = c & 255, row = e >> 4, ch = e & 15;
        cpasync16(dst + row*136 + ch*8, base + (long)(k0+row)*N + n0 + ch*8, 16);
      }
    } else {
      uint32_t* Bs = (uint32_t*)bst;
      const uint32_t* BH = (const uint32_t*)Bhp + (long)bz*sB;
      const uint32_t* BL = (const uint32_t*)Blp + (long)bz*sB;
      #pragma unroll
      for (int c = tid; c < 512; c += 256){
        const uint32_t* base = (c < 256) ? BH : BL;
        uint32_t* dst = Bs + ((c < 256) ? 0 : 8*136);
        int e = c & 255, row = e >> 5, ch = e & 31;
        cpasync16(dst + row*136 + ch*4, base + (long)(k0/2+row)*N + n0 + ch*4, 16);
      }
    }
  };

  const int T = K/16;
  loadT(0, 0);  cp_commit();
  loadT(1, 16); cp_commit();

  for (int i = 0; i < T; i++){
    cp_wait1();
    __syncthreads();
    if (i + 2 < T) loadT((i+2)%3, (i+2)*16);
    cp_commit();

    const char* st = smc + (i%3)*STAGEB;
    const __nv_bfloat16* Ahs = (const __nv_bfloat16*)st;
    const __nv_bfloat16* Als = Ahs + ABF;
    const char* bst = st + ABYTES;

    uint32_t ah[4][4], al[4][4], bh[4][2], bl[4][2];
    #pragma unroll
    for (int mi=0; mi<4; mi++){
      int r = warpM*64 + mi*16 + g;
      ah[mi][0] = *(const uint32_t*)&Ahs[(r  )*AROW + 2*ct  ];
      ah[mi][1] = *(const uint32_t*)&Ahs[(r+8)*AROW + 2*ct  ];
      ah[mi][2] = *(const uint32_t*)&Ahs[(r  )*AROW + 2*ct+8];
      ah[mi][3] = *(const uint32_t*)&Ahs[(r+8)*AROW + 2*ct+8];
      al[mi][0] = *(const uint32_t*)&Als[(r  )*AROW + 2*ct  ];
      al[mi][1] = *(const uint32_t*)&Als[(r+8)*AROW + 2*ct  ];
      al[mi][2] = *(const uint32_t*)&Als[(r  )*AROW + 2*ct+8];
      al[mi][3] = *(const uint32_t*)&Als[(r+8)*AROW + 2*ct+8];
    }
    #pragma unroll
    for (int nj=0; nj<4; nj++){
      int cl = warpN*32 + nj*8 + g;
      if (BI == 2){
        const __nv_bfloat16* Bhs = (const __nv_bfloat16*)bst;
        const __nv_bfloat16* Bls = Bhs + ABF;
        bh[nj][0] = *(const uint32_t*)&Bhs[cl*AROW + 2*ct  ];
        bh[nj][1] = *(const uint32_t*)&Bhs[cl*AROW + 2*ct+8];
        bl[nj][0] = *(const uint32_t*)&Bls[cl*AROW + 2*ct  ];
        bl[nj][1] = *(const uint32_t*)&Bls[cl*AROW + 2*ct+8];
      } else if (BI == 1){
        const uint32_t* Bhs = (const uint32_t*)bst;
        const uint32_t* Bls = Bhs + 8*136;
        bh[nj][0] = Bhs[(ct  )*136 + cl];
        bh[nj][1] = Bhs[(ct+4)*136 + cl];
        bl[nj][0] = Bls[(ct  )*136 + cl];
        bl[nj][1] = Bls[(ct+4)*136 + cl];
      } else {
        const __nv_bfloat16* Bhs = (const __nv_bfloat16*)bst;
        const __nv_bfloat16* Bls = Bhs + 16*136;
        #pragma unroll
        for (int hv=0; hv<2; hv++){
          int kb = 2*ct + hv*8;
          bh[nj][hv] = (uint32_t)(*(const uint16_t*)&Bhs[(kb  )*136 + cl])
                     | ((uint32_t)(*(const uint16_t*)&Bhs[(kb+1)*136 + cl]) << 16);
          bl[nj][hv] = (uint32_t)(*(const uint16_t*)&Bls[(kb  )*136 + cl])
                     | ((uint32_t)(*(const uint16_t*)&Bls[(kb+1)*136 + cl]) << 16);
        }
      }
    }
    #pragma unroll
    for (int mi=0; mi<4; mi++)
      #pragma unroll
      for (int nj=0; nj<4; nj++){
        mma_bf16(acc[mi][nj], ah[mi], bh[nj]);
        mma_bf16(acc[mi][nj], ah[mi], bl[nj]);
        mma_bf16(acc[mi][nj], al[mi], bh[nj]);
      }
  }

  __syncthreads();

  // ---- epilogue
  #pragma unroll
  for (int mi=0; mi<4; mi++){
    int rr[2] = { m0 + warpM*64 + mi*16 + g, m0 + warpM*64 + mi*16 + g + 8 };
    float sc[2] = {0.f,0.f}, of[2] = {0.f,0.f};
    #pragma unroll
    for (int h=0; h<2; h++){
      if (rr[h] < M){
        if (EPI == 1 || EPI == 3 || EPI == 4){ sc[h] = p0[rr[h]]; of[h] = p1[rr[h]]; }
        else if (EPI == 0 || EPI == 5 || EPI == 6){ if (p0) of[h] = p0[rr[h]]; }
      }
    }
    #pragma unroll
    for (int nj=0; nj<4; nj++){
      int n = n0 + warpN*32 + nj*8 + 2*ct;
      #pragma unroll
      for (int h=0; h<2; h++){
        int r = rr[h];
        if (r >= M) continue;
        float wx = acc[mi][nj][2*h], wy = acc[mi][nj][2*h+1];
        if (EPI == 0){ wx += of[h]; wy += of[h]; }
        else if (EPI == 2){
          float2 rv = *(const float2*)&res[(long)r*N + n];
          wx = gamma[0]*wx + rv.x; wy = gamma[0]*wy + rv.y;
        } else if (EPI == 3 || EPI == 4){
          wx = fmaxf(wx*sc[h] + of[h], 0.f);
          wy = fmaxf(wy*sc[h] + of[h], 0.f);
        } else { wx += of[h]; wy += of[h]; }
        if (EPI == 0 || EPI == 2 || EPI == 3){
          float2 w; w.x = wx; w.y = wy;
          *(float2*)&Cm[(long)r*N + n] = w;
        }
        if (EPI >= 3){
          __nv_bfloat16 hx, lx, hy, ly;
          bsplit(wx, hx, lx); bsplit(wy, hy, ly);
          if (EPI == 6){
            Dh[(long)n*ldT + r] = hx;       Dl[(long)n*ldT + r] = lx;
            Dh[(long)(n+1)*ldT + r] = hy;   Dl[(long)(n+1)*ldT + r] = ly;
          } else {
            *(uint32_t*)&Dh[(long)r*N + n] = bpack(hx, hy);
            *(uint32_t*)&Dl[(long)r*N + n] = bpack(lx, ly);
          }
        }
      }
    }
  }
}

// ---------------- softmax row stats ----------------
__global__ __launch_bounds__(256) void softmax_stats_kernel(
    const float* __restrict__ E, const float* __restrict__ M1,
    const float* __restrict__ M2, float* __restrict__ st)
{
  __shared__ float sh[32];
  const int R = NB*NPIX;
  int row = blockIdx.x;
  int mr  = row % NPIX;
  const float* e  = E  + (long)row * NPIX;
  const float* m1 = M1 + (long)mr  * NPIX;
  const float* m2 = M2 + (long)mr  * NPIX;
  int tid = threadIdx.x;
  float ev[9], w1[9], w2[9];
  float mx0=-3.4e38f, mx1=-3.4e38f, mx2=-3.4e38f;
  #pragma unroll
  for (int i=0;i<9;i++){
    int n = tid + i*256;
    ev[i]=e[n]; w1[i]=m1[n]; w2[i]=m2[n];
    mx0 = fmaxf(mx0, ev[i]);
    if (w1[i] > 0.f) mx1 = fmaxf(mx1, ev[i]);
    if (w2[i] > 0.f) mx2 = fmaxf(mx2, ev[i]);
  }
  mx0 = blockMax(mx0, sh); mx1 = blockMax(mx1, sh); mx2 = blockMax(mx2, sh);
  float s0=0.f, s1=0.f, s2=0.f;
  #pragma unroll
  for (int i=0;i<9;i++){
    s0 += __expf(ev[i]-mx0);
    s1 += (w1[i] > 0.f) ? __expf(ev[i]-mx1) : 0.f;
    s2 += (w2[i] > 0.f) ? __expf(ev[i]-mx2) : 0.f;
  }
  s0 = blockSum(s0, sh); s1 = blockSum(s1, sh); s2 = blockSum(s2, sh);
  if (tid == 0){
    st[row]       = mx0;  st[R   + row] = 1.f/s0;
    st[2*R + row] = mx1;  st[3*R + row] = 1.f/s1;
    st[4*R + row] = mx2;  st[5*R + row] = 1.f/s2;
  }
}

// ---------------- attention matrix -> bf16 split ----------------
__global__ __launch_bounds__(256) void attn_mat_kernel(
    const float* __restrict__ E, const float* __restrict__ mask,
    const float* __restrict__ st, __nv_bfloat16* __restrict__ Ahd,
    __nv_bfloat16* __restrict__ Ald, long total4)
{
  const long NN2 = (long)NPIX*NPIX;
  long i4 = (long)blockIdx.x * 256 + threadIdx.x;
  if (i4 >= total4) return;
  long idx = i4 * 4;
  int  b   = (int)(idx / NN2);
  long rem = idx - (long)b * NN2;
  int  mr  = (int)(rem / NPIX);
  float mx   = st[b*NPIX + mr];
  float rinv = st[NB*NPIX + b*NPIX + mr];
  float4 e = *(const float4*)&E[idx];
  float4 a;
  a.x = __expf(e.x-mx)*rinv; a.y = __expf(e.y-mx)*rinv;
  a.z = __expf(e.z-mx)*rinv; a.w = __expf(e.w-mx)*rinv;
  if (mask){
    float4 mk = *(const float4*)&mask[rem];
    if (mk.x <= 0.f) a.x = 0.f;
    if (mk.y <= 0.f) a.y = 0.f;
    if (mk.z <= 0.f) a.z = 0.f;
    if (mk.w <= 0.f) a.w = 0.f;
  }
  __nv_bfloat16 h0,l0,h1,l1,h2,l2,h3,l3;
  bsplit(a.x,h0,l0); bsplit(a.y,h1,l1); bsplit(a.z,h2,l2); bsplit(a.w,h3,l3);
  *(uint32_t*)&Ahd[idx]   = bpack(h0,h1);
  *(uint32_t*)&Ahd[idx+2] = bpack(h2,h3);
  *(uint32_t*)&Ald[idx]   = bpack(l0,l1);
  *(uint32_t*)&Ald[idx+2] = bpack(l2,l3);
}

// ---------------- chl softmax -> bf16 split ----------------
__global__ __launch_bounds__(256) void chl_softmax_kernel(
    const float* __restrict__ E, __nv_bfloat16* __restrict__ Ahd,
    __nv_bfloat16* __restrict__ Ald)
{
  __shared__ float sh[32];
  long row = blockIdx.x;
  const float* e = E + row * CCH;
  int tid = threadIdx.x;
  float v0 = e[tid], v1 = e[tid+256];
  float mn = blockMin(fminf(v0, v1), sh);
  float t0 = __expf(mn - v0), t1 = __expf(mn - v1);
  float s = blockSum(t0 + t1, sh);
  float rinv = 1.f/s;
  __nv_bfloat16 h,l;
  bsplit(t0*rinv, h, l); Ahd[row*CCH + tid]     = h; Ald[row*CCH + tid]     = l;
  bsplit(t1*rinv, h, l); Ahd[row*CCH + tid+256] = h; Ald[row*CCH + tid+256] = l;
}

// ---------------- im2col -> interleaved bf16 split ----------------
__global__ __launch_bounds__(256) void im2col_kernel(const float* __restrict__ X,
    uint32_t* __restrict__ Ch, uint32_t* __restrict__ Cl)
{
  const long total = (long)NB*(KCONV/2)*NPIX;
  long w = (long)blockIdx.x * 256 + threadIdx.x;
  if (w >= total) return;
  int n = (int)(w % NPIX);
  long t = w / NPIX;
  int k2 = (int)(t % (KCONV/2));
  int b  = (int)(t / (KCONV/2));
  int y0 = n / HW, x0 = n - y0*HW;
  float v[2];
  #pragma unroll
  for (int u=0; u<2; u++){
    int k = 2*k2 + u;
    int ic = k/9, kk = k - ic*9;
    int ky = kk/3, kx = kk - ky*3;
    int y = y0 + ky - 1, x = x0 + kx - 1;
    v[u] = (y >= 0 && y < HW && x >= 0 && x < HW)
         ? X[((long)(b*CCH + ic))*NPIX + y*HW + x] : 0.f;
  }
  __nv_bfloat16 h0,l0,h1,l1;
  bsplit(v[0],h0,l0); bsplit(v[1],h1,l1);
  Ch[w] = bpack(h0,h1);
  Cl[w] = bpack(l0,l1);
}

// ---------------- prepass: plain split ----------------
__global__ __launch_bounds__(256) void split_nat_kernel(const float* __restrict__ X,
    __nv_bfloat16* __restrict__ H, __nv_bfloat16* __restrict__ L, long total)
{
  for (long i = (long)blockIdx.x*256 + threadIdx.x; i < total; i += (long)gridDim.x*256){
    __nv_bfloat16 h,l; bsplit(X[i], h, l); H[i] = h; L[i] = l;
  }
}

// ---------------- prepass: x -> channel-pair interleaved ----------------
__global__ __launch_bounds__(256) void x_inter_kernel(const float* __restrict__ X,
    uint32_t* __restrict__ Hd, uint32_t* __restrict__ Ld)
{
  const long total = (long)NB*(CCH/2)*NPIX;
  long w = (long)blockIdx.x*256 + threadIdx.x;
  if (w >= total) return;
  int n = (int)(w % NPIX);
  long t = w / NPIX;
  int c2 = (int)(t % (CCH/2));
  int b  = (int)(t / (CCH/2));
  float v0 = X[((long)(b*CCH + 2*c2  ))*NPIX + n];
  float v1 = X[((long)(b*CCH + 2*c2+1))*NPIX + n];
  __nv_bfloat16 h0,l0,h1,l1;
  bsplit(v0,h0,l0); bsplit(v1,h1,l1);
  Hd[w] = bpack(h0,h1);
  Ld[w] = bpack(l0,l1);
}

// ---------------- host ----------------
template<int BI, int EPI>
static void rg(const __nv_bfloat16* Ah, const __nv_bfloat16* Al, long sA,
               const void* Bh, const void* Bl, long sB,
               float* C, long sC,
               __nv_bfloat16* Dh, __nv_bfloat16* Dl, long sD,
               int M, int N, int K,
               const float* p0, const float* p1,
               const float* res, long sRes, const float* gamma, int ldT)
{
  constexpr int ABYTES = 2*128*24*2;
  constexpr int BBYTES = (BI==2) ? ABYTES : 2*16*136*2;
  constexpr int SMEM = 3*(ABYTES + BBYTES);
  cudaFuncSetAttribute(gemm3_kernel<BI,EPI>,
                       cudaFuncAttributeMaxDynamicSharedMemorySize, SMEM);
  dim3 grid(N/128, (M+127)/128, NB);
  gemm3_kernel<BI,EPI><<<grid, 256, SMEM>>>(Ah, Al, sA, Bh, Bl, sB, C, sC,
                                            Dh, Dl, sD, M, N, K, p0, p1, res, sRes, gamma, ldT);
}

template<typename T>
static T* sym(const void* s){ void* p = nullptr; cudaGetSymbolAddress(&p, s); return (T*)p; }

extern "C" void kernel_launch(void* const* d_in, const int* in_sizes, int n_in,
                              void* d_out, int out_size)
{
  const float* x       = (const float*)d_in[0];
  const float* wq      = (const float*)d_in[1];
  const float* bq      = (const float*)d_in[2];
  const float* wk      = (const float*)d_in[3];
  const float* bk      = (const float*)d_in[4];
  const float* wv0     = (const float*)d_in[5];
  const float* bv0     = (const float*)d_in[6];
  const float* conv1_w = (const float*)d_in[7];
  const float* conv1_s = (const float*)d_in[8];
  const float* conv1_b = (const float*)d_in[9];
  const float* conv2_w = (const float*)d_in[10];
  const float* conv2_s = (const float*)d_in[11];
  const float* conv2_b = (const float*)d_in[12];
  const float* gamma   = (const float*)d_in[13];
  const float* gamma1  = (const float*)d_in[14];
  const float* gamma2  = (const float*)d_in[15];
  const float* c1_qw   = (const float*)d_in[16];
  const float* c1_qs   = (const float*)d_in[17];
  const float* c1_qb   = (const float*)d_in[18];
  const float* c1_ew   = (const float*)d_in[19];
  const float* c1_eb   = (const float*)d_in[20];
  const float* c2_qw   = (const float*)d_in[21];
  const float* c2_qs   = (const float*)d_in[22];
  const float* c2_qb   = (const float*)d_in[23];
  const float* c2_ew   = (const float*)d_in[24];
  const float* c2_eb   = (const float*)d_in[25];
  const float* mask1   = (const float*)d_in[26];
  const float* mask2   = (const float*)d_in[27];

  typedef __nv_bfloat16 bf;
  float* E    = sym<float>(g_E);    float* st   = sym<float>(g_stats);
  float* buf0 = sym<float>(g_buf0); float* buf1 = sym<float>(g_buf1);
  float* out1 = sym<float>(g_out1); float* expd = sym<float>(g_expd);
  bf *wq_h = sym<bf>(g_wq_h), *wq_l = sym<bf>(g_wq_l);
  bf *wk_h = sym<bf>(g_wk_h), *wk_l = sym<bf>(g_wk_l);
  bf *wv_h = sym<bf>(g_wv_h), *wv_l = sym<bf>(g_wv_l);
  bf *cw1_h = sym<bf>(g_cw1_h), *cw1_l = sym<bf>(g_cw1_l);
  bf *cw2_h = sym<bf>(g_cw2_h), *cw2_l = sym<bf>(g_cw2_l);
  bf *qw1_h = sym<bf>(g_qw1_h), *qw1_l = sym<bf>(g_qw1_l);
  bf *qw2_h = sym<bf>(g_qw2_h), *qw2_l = sym<bf>(g_qw2_l);
  bf *ew1_h = sym<bf>(g_ew1_h), *ew1_l = sym<bf>(g_ew1_l);
  bf *ew2_h = sym<bf>(g_ew2_h), *ew2_l = sym<bf>(g_ew2_l);
  uint32_t *xi_h = sym<uint32_t>(g_xi_h), *xi_l = sym<uint32_t>(g_xi_l);
  bf *qT_h = sym<bf>(g_qT_h), *qT_l = sym<bf>(g_qT_l);
  bf *k_h  = sym<bf>(g_k_h),  *k_l  = sym<bf>(g_k_l);
  bf *v_h  = sym<bf>(g_v_h),  *v_l  = sym<bf>(g_v_l);
  bf *at_h = sym<bf>(g_at_h), *at_l = sym<bf>(g_at_l);
  uint32_t *ci_h = sym<uint32_t>(g_ci_h), *ci_l = sym<uint32_t>(g_ci_l);
  bf *b0_h = sym<bf>(g_b0_h), *b0_l = sym<bf>(g_b0_l);
  bf *o1_h = sym<bf>(g_o1_h), *o1_l = sym<bf>(g_o1_l);
  bf *qc_h = sym<bf>(g_qc_h), *qc_l = sym<bf>(g_qc_l);
  bf *e2_h = sym<bf>(g_e2_h), *e2_l = sym<bf>(g_e2_l);
  bf *ac_h = sym<bf>(g_ac_h), *ac_l = sym<bf>(g_ac_l);
  bf *vc_h = sym<bf>(g_vc_h), *vc_l = sym<bf>(g_vc_l);
  float* out = (float*)d_out;

  const long sX  = (long)CCH*NPIX;
  const long sE  = (long)NPIX*NPIX;
  const long sXI = (long)(CCH/2)*NPIX;
  const long sCI = (long)(KCONV/2)*NPIX;
  const long sQT = (long)NPIX*CR;
  const long sK  = (long)CR*NPIX;
  const long sQC = (long)CH4*NPIX;
  const long sE2 = (long)CH4*CCH;
  const long sCC = (long)CCH*CCH;
  const int  R   = NB*NPIX;
  const long total4 = (long)NB*NPIX*NPIX/4;
  const int  amg = (int)((total4 + 255)/256);
  auto gsz = [](long t){ return (int)((t + 255)/256); };

  // ---- prepass splits (weights + x interleave) ----
  split_nat_kernel<<<gsz(CR*CCH),256>>>(wq, wq_h, wq_l, CR*CCH);
  split_nat_kernel<<<gsz(CR*CCH),256>>>(wk, wk_h, wk_l, CR*CCH);
  split_nat_kernel<<<gsz(CCH*CCH),256>>>(wv0, wv_h, wv_l, CCH*CCH);
  split_nat_kernel<<<gsz((long)CCH*KCONV),256>>>(conv1_w, cw1_h, cw1_l, (long)CCH*KCONV);
  split_nat_kernel<<<gsz((long)CCH*KCONV),256>>>(conv2_w, cw2_h, cw2_l, (long)CCH*KCONV);
  split_nat_kernel<<<gsz(CH4*CCH),256>>>(c1_qw, qw1_h, qw1_l, CH4*CCH);
  split_nat_kernel<<<gsz(CH4*CCH),256>>>(c2_qw, qw2_h, qw2_l, CH4*CCH);
  split_nat_kernel<<<gsz(CCH*CH4),256>>>(c1_ew, ew1_h, ew1_l, CCH*CH4);
  split_nat_kernel<<<gsz(CCH*CH4),256>>>(c2_ew, ew2_h, ew2_l, CCH*CH4);
  x_inter_kernel<<<gsz((long)NB*sXI),256>>>(x, xi_h, xi_l);

  // ---- Q (transposed split), K, V ----
  rg<1,6>(wq_h, wq_l, 0, xi_h, xi_l, sXI, nullptr,0, qT_h, qT_l, sQT,
          CR, NPIX, CCH, bq, nullptr, nullptr,0, nullptr, CR);
  rg<1,5>(wk_h, wk_l, 0, xi_h, xi_l, sXI, nullptr,0, k_h, k_l, sK,
          CR, NPIX, CCH, bk, nullptr, nullptr,0, nullptr, 0);
  rg<1,5>(wv_h, wv_l, 0, xi_h, xi_l, sXI, nullptr,0, v_h, v_l, sX,
          CCH, NPIX, CCH, bv0, nullptr, nullptr,0, nullptr, 0);

  // ---- energy = qT * k ----
  rg<0,0>(qT_h, qT_l, sQT, k_h, k_l, sK, E, sE, nullptr,nullptr,0,
          NPIX, NPIX, CR, nullptr, nullptr, nullptr,0, nullptr, 0);

  softmax_stats_kernel<<<R, 256>>>(E, mask1, mask2, st);

  // ---- pass 0 ----
  attn_mat_kernel<<<amg, 256>>>(E, nullptr, st, at_h, at_l, total4);
  rg<2,2>(v_h, v_l, sX, at_h, at_l, sE, buf1, sX, nullptr,nullptr,0,
          CCH, NPIX, NPIX, nullptr, nullptr, (const float*)x, sX, gamma, 0);
  im2col_kernel<<<gsz((long)NB*sCI), 256>>>(buf1, ci_h, ci_l);
  rg<1,3>(cw1_h, cw1_l, 0, ci_h, ci_l, sCI, buf0, sX, b0_h, b0_l, sX,
          CCH, NPIX, KCONV, conv1_s, conv1_b, nullptr,0, nullptr, 0);

  // chl #1
  rg<0,4>(qw1_h, qw1_l, 0, b0_h, b0_l, sX, nullptr,0, qc_h, qc_l, sQC,
          CH4, NPIX, CCH, c1_qs, c1_qb, nullptr,0, nullptr, 0);
  rg<2,5>(qc_h, qc_l, sQC, b0_h, b0_l, sX, nullptr,0, e2_h, e2_l, sE2,
          CH4, CCH, NPIX, nullptr, nullptr, nullptr,0, nullptr, 0);
  rg<0,0>(ew1_h, ew1_l, 0, e2_h, e2_l, sE2, expd, sCC, nullptr,nullptr,0,
          CCH, CCH, CH4, c1_eb, nullptr, nullptr,0, nullptr, 0);
  chl_softmax_kernel<<<NB*CCH, 256>>>(expd, ac_h, ac_l);
  rg<0,5>(ac_h, ac_l, sCC, b0_h, b0_l, sX, nullptr,0, vc_h, vc_l, sX,
          CCH, NPIX, CCH, nullptr, nullptr, nullptr,0, nullptr, 0);

  // ---- pass 1 ----
  attn_mat_kernel<<<amg, 256>>>(E, mask1, st + 2*R, at_h, at_l, total4);
  rg<2,2>(vc_h, vc_l, sX, at_h, at_l, sE, buf1, sX, nullptr,nullptr,0,
          CCH, NPIX, NPIX, nullptr, nullptr, buf0, sX, gamma1, 0);
  im2col_kernel<<<gsz((long)NB*sCI), 256>>>(buf1, ci_h, ci_l);
  rg<1,3>(cw2_h, cw2_l, 0, ci_h, ci_l, sCI, out1, sX, o1_h, o1_l, sX,
          CCH, NPIX, KCONV, conv2_s, conv2_b, nullptr,0, nullptr, 0);

  // chl #2
  rg<0,4>(qw2_h, qw2_l, 0, o1_h, o1_l, sX, nullptr,0, qc_h, qc_l, sQC,
          CH4, NPIX, CCH, c2_qs, c2_qb, nullptr,0, nullptr, 0);
  rg<2,5>(qc_h, qc_l, sQC, o1_h, o1_l, sX, nullptr,0, e2_h, e2_l, sE2,
          CH4, CCH, NPIX, nullptr, nullptr, nullptr,0, nullptr, 0);
  rg<0,0>(ew2_h, ew2_l, 0, e2_h, e2_l, sE2, expd, sCC, nullptr,nullptr,0,
          CCH, CCH, CH4, c2_eb, nullptr, nullptr,0, nullptr, 0);
  chl_softmax_kernel<<<NB*CCH, 256>>>(expd, ac_h, ac_l);
  rg<0,5>(ac_h, ac_l, sCC, o1_h, o1_l, sX, nullptr,0, vc_h, vc_l, sX,
          CCH, NPIX, CCH, nullptr, nullptr, nullptr,0, nullptr, 0);

  // ---- pass 2 -> out ----
  attn_mat_kernel<<<amg, 256>>>(E, mask2, st + 4*R, at_h, at_l, total4);
  rg<2,2>(vc_h, vc_l, sX, at_h, at_l, sE, out, sX, nullptr,nullptr,0,
          CCH, NPIX, NPIX, nullptr, nullptr, out1, sX, gamma2, 0);

  (void)in_sizes; (void)n_in; (void)out_size;
}